// round 9
// baseline (speedup 1.0000x reference)
#include <cuda_runtime.h>
#include <cuda_bf16.h>
#include <math.h>
#include <float.h>
#include <stdint.h>

#define S   512
#define Bn  256
#define DIN 202
#define Hh  100
#define Tt  19
#define SB  (S*Bn)

// ---------------- scratch (device globals; no runtime allocation) ----------
__device__ float g_xp[SB * 200];     // input projections (biases included)
__device__ float g_h [SB * 200];     // concatenated hidden states
__device__ float g_probs[SB * Tt];   // softmax emissions
__device__ float g_nd[S];            // per-sequence (num - den)

// packed fp32x2 FMA (Blackwell FFMA2; PTX >= sm_100, family-generic)
__device__ __forceinline__ void fma2(unsigned long long& d,
                                     unsigned long long a, unsigned long long b) {
    asm("fma.rn.f32x2 %0, %1, %2, %0;" : "+l"(d) : "l"(a), "l"(b));
}
__device__ __forceinline__ unsigned long long pack2(float lo, float hi) {
    unsigned long long r;
    asm("mov.b64 %0, {%1, %2};" : "=l"(r) : "f"(lo), "f"(hi));
    return r;
}
__device__ __forceinline__ void unpack2(unsigned long long v, float& lo, float& hi) {
    asm("mov.b64 {%0, %1}, %2;" : "=f"(lo), "=f"(hi) : "l"(v));
}

// ============================================================================
// Stage 1: persistent bf16 GEMM via mma.sync.m16n8k16.
// D[131072, 200] = x[131072, 202] @ W[200, 202]^T, K padded to 208 (13x16),
// N tiled as 25 x 8. W in smem bf16 once per block; full 128x208 A tile per
// iteration -> ONE barrier pair per tile. Strides 108 words: bank map
// (12g + tig) mod 32 hits all 32 banks -> conflict-free fragment LDS.
// ============================================================================
#define KCHUNKS 13
#define NTILES  25
#define MTILES  (SB / 128)            // 1024
#define RSTRIDE 108                   // words (uint32) per row, A and B
#define SM_B    1024
#define B_BYTES (200 * RSTRIDE * 4)   // 86400
#define SM_A    (SM_B + B_BYTES)      // 87424
#define A_BYTES (128 * RSTRIDE * 4)   // 55296
#define PROJ_SMEM (SM_A + A_BYTES)    // 142720

__global__ __launch_bounds__(256, 1) void proj_mma(
    const float* __restrict__ x,
    const float* __restrict__ Wf, const float* __restrict__ Wb,
    const float* __restrict__ bif, const float* __restrict__ bhf,
    const float* __restrict__ bib, const float* __restrict__ bhb)
{
    extern __shared__ __align__(16) char smem[];
    float*    bias_s = (float*)smem;
    uint32_t* Bw     = (uint32_t*)(smem + SM_B);
    uint32_t* Aw     = (uint32_t*)(smem + SM_A);

    const int tid = threadIdx.x;
    const int w   = tid >> 5, lane = tid & 31;
    const int g   = lane >> 2, tig = lane & 3;

    if (tid < 100) {
        bias_s[tid]       = bif[tid] + bhf[tid];
        bias_s[100 + tid] = bib[tid] + bhb[tid];
    }

    // ---- W -> smem bf16 once (every word incl. k-pad written) ----
    for (int idx = tid; idx < 200 * 104; idx += 256) {
        const int n = idx / 104, j = idx % 104;
        uint32_t v = 0;
        if (j < 101) {
            const float2 f = ((const float2*)((n < 100) ? (Wf + (size_t)n * DIN)
                                                        : (Wb + (size_t)(n - 100) * DIN)))[j];
            __nv_bfloat162 h2 = __floats2bfloat162_rn(f.x, f.y);
            v = *(uint32_t*)&h2;
        }
        Bw[n * RSTRIDE + j] = v;
    }
    __syncthreads();

    for (int tile = blockIdx.x; tile < MTILES; tile += gridDim.x) {
        // ---- A tile fill (coalesced; pads written zero) ----
        for (int idx = tid; idx < 128 * 104; idx += 256) {
            const int r = idx / 104, j = idx % 104;
            uint32_t v = 0;
            if (j < 101) {
                const float2 f = ((const float2*)(x + (size_t)(tile * 128 + r) * DIN))[j];
                __nv_bfloat162 h2 = __floats2bfloat162_rn(f.x, f.y);
                v = *(uint32_t*)&h2;
            }
            Aw[r * RSTRIDE + j] = v;
        }
        __syncthreads();

        float c[NTILES][4];
        #pragma unroll
        for (int j = 0; j < NTILES; j++)
            #pragma unroll
            for (int q = 0; q < 4; q++) c[j][q] = 0.f;

        const int r0 = w * 16 + g, r1 = r0 + 8;
        #pragma unroll 1
        for (int kc = 0; kc < KCHUNKS; kc++) {
            const int kw = kc * 8 + tig;
            const uint32_t a0 = Aw[r0 * RSTRIDE + kw];
            const uint32_t a1 = Aw[r1 * RSTRIDE + kw];
            const uint32_t a2 = Aw[r0 * RSTRIDE + kw + 4];
            const uint32_t a3 = Aw[r1 * RSTRIDE + kw + 4];
            #pragma unroll
            for (int j = 0; j < NTILES; j++) {
                const uint32_t* bp = Bw + (8 * j + g) * RSTRIDE + kw;
                const uint32_t b0 = bp[0];
                const uint32_t b1 = bp[4];
                asm volatile(
                    "mma.sync.aligned.m16n8k16.row.col.f32.bf16.bf16.f32 "
                    "{%0,%1,%2,%3}, {%4,%5,%6,%7}, {%8,%9}, {%0,%1,%2,%3};"
                    : "+f"(c[j][0]), "+f"(c[j][1]), "+f"(c[j][2]), "+f"(c[j][3])
                    : "r"(a0), "r"(a1), "r"(a2), "r"(a3), "r"(b0), "r"(b1));
            }
        }

        // epilogue: thread holds rows g/g+8 of its warp strip, cols 8j+2tig..+1
        const int m0 = tile * 128 + w * 16;
        #pragma unroll
        for (int j = 0; j < NTILES; j++) {
            const int col = 8 * j + tig * 2;
            const float bx = bias_s[col], by = bias_s[col + 1];
            *(float2*)&g_xp[(size_t)(m0 + g)     * 200 + col] =
                make_float2(c[j][0] + bx, c[j][1] + by);
            *(float2*)&g_xp[(size_t)(m0 + g + 8) * 200 + col] =
                make_float2(c[j][2] + bx, c[j][3] + by);
        }
        __syncthreads();   // MMA reads done before next tile's A fill
    }
}

// ============================================================================
// Stage 2: recurrent tanh scan. 512 blocks (dir,b). Whh row packed f32x2 in
// registers (50 FFMA2 per dot instead of 100 FFMA), 4-deep xp prefetch ring,
// 4 packed accumulator chains, fast tanh. Full fp32 precision.
// ============================================================================
__global__ __launch_bounds__(128) void rnn_scan(
    const float* __restrict__ Whf, const float* __restrict__ Whb)
{
    const int dir = (blockIdx.x >= Bn) ? 1 : 0;
    const int b   = dir ? (blockIdx.x - Bn) : blockIdx.x;
    const int tid = threadIdx.x;
    const float* Whh = dir ? Whb : Whf;
    const bool act = tid < 100;

    __shared__ __align__(16) float hs[2][100];

    unsigned long long w2[50];
    if (act) {
        #pragma unroll
        for (int j = 0; j < 50; j++)
            w2[j] = pack2(Whh[tid * 100 + 2 * j], Whh[tid * 100 + 2 * j + 1]);
        hs[0][tid] = 0.f;
    }

    const size_t base = (size_t)b * 200 + (size_t)dir * 100 + tid;
    float pf[4];
    #pragma unroll
    for (int i = 0; i < 4; i++) {
        int t = dir ? (S - 1 - i) : i;
        pf[i] = act ? g_xp[(size_t)t * (Bn * 200) + base] : 0.f;
    }
    __syncthreads();

    int p = 0;
    for (int step = 0; step < S; step++) {
        const int t = dir ? (S - 1 - step) : step;
        float acc = pf[step & 3];
        if (step + 4 < S && act) {
            int t4 = dir ? (S - 1 - (step + 4)) : (step + 4);
            pf[step & 3] = g_xp[(size_t)t4 * (Bn * 200) + base];
        }
        if (act) {
            unsigned long long a0 = pack2(acc, 0.f), a1 = 0ull, a2 = 0ull, a3 = 0ull;
            #pragma unroll
            for (int jj = 0; jj < 25; jj++) {
                ulonglong2 hh = *(const ulonglong2*)&hs[p][jj * 4];
                if (jj & 1) { fma2(a2, hh.x, w2[2 * jj]); fma2(a3, hh.y, w2[2 * jj + 1]); }
                else        { fma2(a0, hh.x, w2[2 * jj]); fma2(a1, hh.y, w2[2 * jj + 1]); }
            }
            float f0, f1, f2, f3, f4, f5, f6, f7;
            unpack2(a0, f0, f1); unpack2(a1, f2, f3);
            unpack2(a2, f4, f5); unpack2(a3, f6, f7);
            float s = ((f0 + f1) + (f2 + f3)) + ((f4 + f5) + (f6 + f7));
            float e = __expf(2.f * s);                    // tanh = 1 - 2/(e^{2s}+1)
            float nh = 1.f - __fdividef(2.f, e + 1.f);
            hs[p ^ 1][tid] = nh;
            g_h[(size_t)t * (Bn * 200) + base] = nh;
        }
        __syncthreads();
        p ^= 1;
    }
}

// ============================================================================
// Stage 3: logits = h @ W_tag^T + b_tag, softmax over T=19. Warp per row,
// 256-thread blocks, float4 h loads.
// ============================================================================
__global__ __launch_bounds__(256) void tag_softmax(
    const float* __restrict__ Wtag, const float* __restrict__ btag)
{
    __shared__ __align__(16) float hrow[8][200];
    __shared__ __align__(16) float Wt[200 * Tt];   // [h][t]
    __shared__ float bt[Tt];
    const int tid = threadIdx.x;

    for (int idx = tid; idx < 200 * Tt; idx += 256) {
        int h = idx / Tt, t = idx % Tt;
        Wt[idx] = Wtag[t * 200 + h];
    }
    if (tid < Tt) bt[tid] = btag[tid];
    __syncthreads();

    const int warp = tid >> 5, lane = tid & 31;
    const unsigned FULL = 0xffffffffu;
    for (int row = blockIdx.x * 8 + warp; row < SB; row += gridDim.x * 8) {
        const float4* hr4 = (const float4*)(g_h + (size_t)row * 200);
        float4* dst4 = (float4*)hrow[warp];
        for (int i = lane; i < 50; i += 32) dst4[i] = hr4[i];
        __syncwarp();
        float acc = 0.f;
        if (lane < Tt) {
            float a0 = 0.f, a1 = 0.f, a2 = 0.f, a3 = 0.f;
            #pragma unroll
            for (int h4 = 0; h4 < 50; h4++) {
                float4 hv = *(const float4*)&hrow[warp][h4 * 4];
                a0 = fmaf(hv.x, Wt[(h4 * 4 + 0) * Tt + lane], a0);
                a1 = fmaf(hv.y, Wt[(h4 * 4 + 1) * Tt + lane], a1);
                a2 = fmaf(hv.z, Wt[(h4 * 4 + 2) * Tt + lane], a2);
                a3 = fmaf(hv.w, Wt[(h4 * 4 + 3) * Tt + lane], a3);
            }
            acc = bt[lane] + ((a0 + a1) + (a2 + a3));
        }
        float v = (lane < Tt) ? acc : -FLT_MAX;
        float m = v;
        #pragma unroll
        for (int o = 16; o; o >>= 1) m = fmaxf(m, __shfl_xor_sync(FULL, m, o));
        float e = (lane < Tt) ? __expf(acc - m) : 0.f;
        float ssum = e;
        #pragma unroll
        for (int o = 16; o; o >>= 1) ssum += __shfl_xor_sync(FULL, ssum, o);
        if (lane < Tt) g_probs[(size_t)row * Tt + lane] = e / ssum;
        __syncwarp();
    }
}

// ============================================================================
// Stage 4: fused CRF numerator + forward. TWO sequences per warp (interleaved
// independent chains -> 2x ILP on the exp->dot->log critical path).
// LSE shift = lane-0 alpha broadcast (spread bounded: emissions in (0,1)).
// ============================================================================
__device__ __forceinline__ int clamp_tag(int t) {
    return t < 0 ? 0 : (t >= Tt ? Tt - 1 : t);
}

__global__ __launch_bounds__(128) void crf_kernel(
    const int* __restrict__ y, const float* __restrict__ trans,
    const float* __restrict__ start_t, const float* __restrict__ end_t)
{
    __shared__ __align__(16) float pA[4][32], pB[4][32];
    const int tid = threadIdx.x, warp = tid >> 5, lane = tid & 31;
    const int n0 = (blockIdx.x * 4 + warp) * 2, n1 = n0 + 1;
    const unsigned FULL = 0xffffffffu;
    const bool val = lane < Tt;
    const int lanec = val ? lane : (Tt - 1);

    const int* yrA = y + (size_t)n0 * Bn;
    const int* yrB = y + (size_t)n1 * Bn;
    const float* emA = g_probs + (size_t)n0 * Bn * Tt;
    const float* emB = g_probs + (size_t)n1 * Bn * Tt;

    // ---- numerators (both) ----
    float numA = 0.f, numB = 0.f;
    for (int l = lane; l < Bn; l += 32) {
        int ta = clamp_tag(yrA[l]), tb = clamp_tag(yrB[l]);
        numA += emA[l * Tt + ta];
        numB += emB[l * Tt + tb];
        if (l + 1 < Bn) {
            numA += trans[ta * Tt + clamp_tag(yrA[l + 1])];
            numB += trans[tb * Tt + clamp_tag(yrB[l + 1])];
        }
    }
    #pragma unroll
    for (int o = 16; o; o >>= 1) {
        numA += __shfl_xor_sync(FULL, numA, o);
        numB += __shfl_xor_sync(FULL, numB, o);
    }

    // ---- forward algorithm (interleaved A/B) ----
    float et[Tt];
    #pragma unroll
    for (int i = 0; i < Tt; i++)
        et[i] = val ? __expf(trans[i * Tt + lanec]) : 0.f;

    float aA = val ? (start_t[lanec] + emA[lanec]) : 0.f;
    float aB = val ? (start_t[lanec] + emB[lanec]) : 0.f;
    float eA1 = emA[1 * Tt + lanec], eA2 = emA[2 * Tt + lanec];
    float eB1 = emB[1 * Tt + lanec], eB2 = emB[2 * Tt + lanec];

    for (int l = 1; l < Bn; l++) {
        float ecA = eA1, ecB = eB1;
        eA1 = eA2; eB1 = eB2;
        if (l + 2 < Bn) {
            eA2 = emA[(size_t)(l + 2) * Tt + lanec];
            eB2 = emB[(size_t)(l + 2) * Tt + lanec];
        }
        float mA = __shfl_sync(FULL, aA, 0);
        float mB = __shfl_sync(FULL, aB, 0);
        float pvA = val ? __expf(aA - mA) : 0.f;
        float pvB = val ? __expf(aB - mB) : 0.f;
        pA[warp][lane] = pvA;
        pB[warp][lane] = pvB;
        __syncwarp();
        float sA0 = 0.f, sA1 = 0.f, sB0 = 0.f, sB1 = 0.f;
        #pragma unroll
        for (int i = 0; i < 10; i++) {
            sA0 = fmaf(pA[warp][i], et[i], sA0);
            sB0 = fmaf(pB[warp][i], et[i], sB0);
        }
        #pragma unroll
        for (int i = 10; i < Tt; i++) {
            sA1 = fmaf(pA[warp][i], et[i], sA1);
            sB1 = fmaf(pB[warp][i], et[i], sB1);
        }
        aA = mA + __logf(sA0 + sA1) + ecA;
        aB = mB + __logf(sB0 + sB1) + ecB;
        __syncwarp();
    }

    float vA = val ? (aA + end_t[lanec]) : -FLT_MAX;
    float vB = val ? (aB + end_t[lanec]) : -FLT_MAX;
    float mA = vA, mB = vB;
    #pragma unroll
    for (int o = 16; o; o >>= 1) {
        mA = fmaxf(mA, __shfl_xor_sync(FULL, mA, o));
        mB = fmaxf(mB, __shfl_xor_sync(FULL, mB, o));
    }
    float eA = val ? __expf(vA - mA) : 0.f;
    float eB = val ? __expf(vB - mB) : 0.f;
    float sA = eA, sB = eB;
    #pragma unroll
    for (int o = 16; o; o >>= 1) {
        sA += __shfl_xor_sync(FULL, sA, o);
        sB += __shfl_xor_sync(FULL, sB, o);
    }
    if (lane == 0) {
        g_nd[n0] = (numA + start_t[clamp_tag(yrA[0])] + end_t[clamp_tag(yrA[Bn - 1])])
                 - (mA + __logf(sA));
        g_nd[n1] = (numB + start_t[clamp_tag(yrB[0])] + end_t[clamp_tag(yrB[Bn - 1])])
                 - (mB + __logf(sB));
    }
}

// ============================================================================
// Stage 5: deterministic final reduction -> scalar.
// ============================================================================
__global__ void final_reduce(float* __restrict__ out)
{
    __shared__ float sh[512];
    int tid = threadIdx.x;
    sh[tid] = g_nd[tid];
    __syncthreads();
    for (int st = 256; st; st >>= 1) {
        if (tid < st) sh[tid] += sh[tid + st];
        __syncthreads();
    }
    if (tid == 0) out[0] = sh[0];
}

// ---------------------------------------------------------------------------
extern "C" void kernel_launch(void* const* d_in, const int* in_sizes, int n_in,
                              void* d_out, int out_size)
{
    (void)in_sizes; (void)n_in; (void)out_size;
    const float* x      = (const float*)d_in[0];
    const int*   y      = (const int*)d_in[1];    // int32 (JAX x64 disabled)
    const float* Wihf   = (const float*)d_in[2];
    const float* Whhf   = (const float*)d_in[3];
    const float* bihf   = (const float*)d_in[4];
    const float* bhhf   = (const float*)d_in[5];
    const float* Wihb   = (const float*)d_in[6];
    const float* Whhb   = (const float*)d_in[7];
    const float* bihb   = (const float*)d_in[8];
    const float* bhhb   = (const float*)d_in[9];
    const float* Wtag   = (const float*)d_in[10];
    const float* btag   = (const float*)d_in[11];
    const float* startt = (const float*)d_in[12];
    const float* endt   = (const float*)d_in[13];
    const float* trans  = (const float*)d_in[14];

    cudaFuncSetAttribute(proj_mma, cudaFuncAttributeMaxDynamicSharedMemorySize, PROJ_SMEM);

    proj_mma   <<<148, 256, PROJ_SMEM>>>(x, Wihf, Wihb, bihf, bhhf, bihb, bhhb);
    rnn_scan   <<<512, 128>>>(Whhf, Whhb);
    tag_softmax<<<1024, 256>>>(Wtag, btag);
    crf_kernel <<<64, 128>>>(y, trans, startt, endt);
    final_reduce<<<1, 512>>>((float*)d_out);
}